// round 15
// baseline (speedup 1.0000x reference)
#include <cuda_runtime.h>
#include <cuda_bf16.h>
#include <cuda_fp16.h>
#include <cstdint>

#define NIN 128
#define TM  64

// ---- SMEM map (bytes), per CTA (2 CTAs/SM) ----
// GEMM1 A (inter): bf16 16x16 tiles, 512B, idx = mt*8 + kc (32 tiles/half)
// GEMM2 A (h): fp16 16x16 tiles, 512B, idx = mtile*16 + kc (64 tiles, 32KB), overwrites inter
#define OFF_AHI 0
#define OFF_ALO 32768
#define OFF_BAS 65536                 // 64 * 17 * 4 = 4352
#define OFF_OUT 69888                 // 64 * 132 * 4 = 33792
#define SMEM_BYTES 103680

// ---- device scratch: fragment-ordered weights (coalesced 512B warp spans) ----
// W1 hi/lo: [ks(8)][wn(4)][g(4)][lane(32)][word(4)]  (16384 words each, bf16 pairs)
// W2 fp16 : [t(128)][wn(4)][g(4)][lane(32)][word(4)] (262144 words, fp16 pairs)
__device__ __align__(16) unsigned g_W1v_hi[16384];
__device__ __align__(16) unsigned g_W1v_lo[16384];
__device__ __align__(16) unsigned g_W2f[262144];
__device__ int g_idx64;

// -------- helpers --------
__device__ __forceinline__ uint32_t smem_u32(const void* p) {
    uint32_t a;
    asm("{ .reg .u64 t; cvta.to.shared.u64 t, %1; cvt.u32.u64 %0, t; }" : "=r"(a) : "l"(p));
    return a;
}
__device__ __forceinline__ unsigned pk(float x0, float x1, unsigned& lo) {
    __nv_bfloat16 h0 = __float2bfloat16(x0), h1 = __float2bfloat16(x1);
    float r0 = x0 - __bfloat162float(h0);
    float r1 = x1 - __bfloat162float(h1);
    __nv_bfloat16 l0 = __float2bfloat16(r0), l1 = __float2bfloat16(r1);
    lo = ((unsigned)__bfloat16_as_ushort(l1) << 16) | (unsigned)__bfloat16_as_ushort(l0);
    return ((unsigned)__bfloat16_as_ushort(h1) << 16) | (unsigned)__bfloat16_as_ushort(h0);
}
__device__ __forceinline__ unsigned h2pk(float x0, float x1) {   // x0 -> low half
    unsigned u;
    asm("cvt.rn.f16x2.f32 %0, %1, %2;" : "=r"(u) : "f"(x1), "f"(x0));
    return u;
}
__device__ __forceinline__ void st128s(uint32_t a, unsigned x, unsigned y, unsigned z, unsigned w) {
    asm volatile("st.shared.v4.b32 [%0], {%1,%2,%3,%4};" :: "r"(a), "r"(x), "r"(y), "r"(z), "r"(w) : "memory");
}
__device__ __forceinline__ void sts32(uint32_t a, unsigned v) {
    asm volatile("st.shared.b32 [%0], %1;" :: "r"(a), "r"(v) : "memory");
}
__device__ __forceinline__ void ldm4(unsigned (&a)[4], uint32_t addr) {
    asm volatile("ldmatrix.sync.aligned.m8n8.x4.shared.b16 {%0,%1,%2,%3}, [%4];"
                 : "=r"(a[0]), "=r"(a[1]), "=r"(a[2]), "=r"(a[3]) : "r"(addr));
}
__device__ __forceinline__ void mma4(float (&d)[4], const unsigned (&a)[4], unsigned b0, unsigned b1) {
    asm volatile(
        "mma.sync.aligned.m16n8k16.row.col.f32.bf16.bf16.f32 "
        "{%0,%1,%2,%3},{%4,%5,%6,%7},{%8,%9},{%0,%1,%2,%3};\n"
        : "+f"(d[0]), "+f"(d[1]), "+f"(d[2]), "+f"(d[3])
        : "r"(a[0]), "r"(a[1]), "r"(a[2]), "r"(a[3]), "r"(b0), "r"(b1));
}
__device__ __forceinline__ void mma4h(float (&d)[4], const unsigned (&a)[4], unsigned b0, unsigned b1) {
    asm volatile(
        "mma.sync.aligned.m16n8k16.row.col.f32.f16.f16.f32 "
        "{%0,%1,%2,%3},{%4,%5,%6,%7},{%8,%9},{%0,%1,%2,%3};\n"
        : "+f"(d[0]), "+f"(d[1]), "+f"(d[2]), "+f"(d[3])
        : "r"(a[0]), "r"(a[1]), "r"(a[2]), "r"(a[3]), "r"(b0), "r"(b1));
}

// -------- prep kernels --------
__global__ void detect_idx_kernel(const unsigned* __restrict__ idx_raw) {
    if (threadIdx.x == 0) {
        unsigned nz = 0;
        #pragma unroll 1
        for (int k = 0; k < 64; k++) nz |= idx_raw[2 * k + 1];
        g_idx64 = (nz == 0) ? 1 : 0;  // int64 values < 2^31 -> high words all zero
    }
}

// W1 [128,256] -> [ks(8)][wn(4)][g(4)][lane][word]; e = g*4+word; nt = e>>1; khalf = e&1
__global__ void prep_w1_kernel(const float* __restrict__ W1) {
    int i = blockIdx.x * 256 + threadIdx.x;        // 16384
    int word = i & 3, lane = (i >> 2) & 31, g = (i >> 7) & 3, wn = (i >> 9) & 3, ks = i >> 11;
    int q = lane & 3, r = lane >> 2;
    int e = g * 4 + word;
    int nt = e >> 1, khalf = e & 1;
    int kpair = ks * 8 + khalf * 4 + q;
    int col = wn * 64 + nt * 8 + r;
    float x0 = W1[(2 * kpair) * 256 + col];
    float x1 = W1[(2 * kpair + 1) * 256 + col];
    unsigned lo, hi = pk(x0, x1, lo);
    g_W1v_hi[i] = hi; g_W1v_lo[i] = lo;
}

// W2 [256,2048] -> fp16 pairs [t(128)][wn(4)][g(4)][lane][word]; e = g*4+word
// t = pass*16 + kstep; nt = e>>1; khalf = e&1; k = kstep*16 + khalf*8 + 2q; col = pass*256 + wn*64 + nt*8 + r
__global__ void prep_w2_kernel(const float* __restrict__ W2) {
    int i = blockIdx.x * 256 + threadIdx.x;        // 262144
    int word = i & 3, lane = (i >> 2) & 31, g = (i >> 7) & 3, wn = (i >> 9) & 3, t = i >> 11;
    int q = lane & 3, r = lane >> 2;
    int e = g * 4 + word;
    int nt = e >> 1, khalf = e & 1;
    int kstep = t & 15, pass = t >> 4;
    int k = kstep * 16 + khalf * 8 + 2 * q;
    int col = pass * 256 + wn * 64 + nt * 8 + r;
    g_W2f[i] = h2pk(W2[k * 2048 + col], W2[(k + 1) * 2048 + col]);
}

// -------- main kernel: 256 threads (8 warps, M2 x N4 split), TM=64, 2 CTAs/SM --------
__global__ void __launch_bounds__(256, 2) pilayer_kernel(
    const float* __restrict__ prop, const void* __restrict__ idxi_raw,
    const void* __restrict__ idxj_raw, const float* __restrict__ basis,
    float* __restrict__ out, int P)
{
    extern __shared__ __align__(1024) char smem[];
    const uint32_t su = smem_u32(smem);
    float* sBas = (float*)(smem + OFF_BAS);
    float* sOut = (float*)(smem + OFF_OUT);

    const int tid = threadIdx.x;
    const int w = tid >> 5, lane = tid & 31, q = lane & 3, r = lane >> 2;
    const int wm = w >> 2, wn = w & 3;
    const int m0 = blockIdx.x * TM;
    const int mvalid = min(TM, P - m0);
    const bool is64 = (g_idx64 != 0);

    // per-lane ldmatrix offset within a 512B (16 rows x 32B) tile
    const int rL = (lane & 7) + (lane & 8);
    const int hL = lane >> 4;
    const uint32_t lmoff = (uint32_t)((rL * 32 + hL * 16) ^ ((rL & 4) << 2));
    const uint32_t aHiB = su + OFF_AHI + lmoff;
    const uint32_t aLoB = su + OFF_ALO + lmoff;

    // ---- gather: inter = prop[idx_i] + prop[idx_j]; bf16 hi/lo split, swizzled tiles ----
    {
        const int m = tid >> 2, qtr = tid & 3;     // 4 threads per row, 32 k-cols each
        const int mt = m >> 4, rr = m & 15;
        const unsigned swz = (unsigned)((rr & 4) << 2);
        const uint32_t o0 = (uint32_t)((rr * 32) ^ swz);
        const uint32_t o1 = o0 ^ 16u;
        if (m < mvalid) {
            long long e = (long long)(m0 + m);
            long long ia, ja;
            if (is64) { ia = ((const long long*)idxi_raw)[e]; ja = ((const long long*)idxj_raw)[e]; }
            else      { ia = ((const int*)idxi_raw)[e];       ja = ((const int*)idxj_raw)[e]; }
            const float4* pi = (const float4*)(prop + ia * NIN);
            const float4* pj = (const float4*)(prop + ja * NIN);
            #pragma unroll
            for (int kc = 0; kc < 2; kc++) {
                const int kcg = qtr * 2 + kc;
                const uint32_t tb = (uint32_t)((mt * 8 + kcg) * 512);
                float4 A0 = pi[kcg * 4], A1 = pi[kcg * 4 + 1], A2 = pi[kcg * 4 + 2], A3 = pi[kcg * 4 + 3];
                float4 B0 = pj[kcg * 4], B1 = pj[kcg * 4 + 1], B2 = pj[kcg * 4 + 2], B3 = pj[kcg * 4 + 3];
                unsigned h0, h1, h2, h3, h4, h5, h6, h7, l0, l1, l2, l3, l4, l5, l6, l7;
                h0 = pk(A0.x + B0.x, A0.y + B0.y, l0);
                h1 = pk(A0.z + B0.z, A0.w + B0.w, l1);
                h2 = pk(A1.x + B1.x, A1.y + B1.y, l2);
                h3 = pk(A1.z + B1.z, A1.w + B1.w, l3);
                h4 = pk(A2.x + B2.x, A2.y + B2.y, l4);
                h5 = pk(A2.z + B2.z, A2.w + B2.w, l5);
                h6 = pk(A3.x + B3.x, A3.y + B3.y, l6);
                h7 = pk(A3.z + B3.z, A3.w + B3.w, l7);
                st128s(su + OFF_AHI + tb + o0, h0, h1, h2, h3);
                st128s(su + OFF_AHI + tb + o1, h4, h5, h6, h7);
                st128s(su + OFF_ALO + tb + o0, l0, l1, l2, l3);
                st128s(su + OFF_ALO + tb + o1, l4, l5, l6, l7);
            }
        } else {
            #pragma unroll
            for (int kc = 0; kc < 2; kc++) {
                const uint32_t tb = (uint32_t)((mt * 8 + qtr * 2 + kc) * 512);
                st128s(su + OFF_AHI + tb + o0, 0, 0, 0, 0);
                st128s(su + OFF_AHI + tb + o1, 0, 0, 0, 0);
                st128s(su + OFF_ALO + tb + o0, 0, 0, 0, 0);
                st128s(su + OFF_ALO + tb + o1, 0, 0, 0, 0);
            }
        }
        // basis rows (zero-padded past mvalid): each thread one float4
        float4 b0;
        if (m < mvalid) b0 = ((const float4*)(basis + (size_t)(m0 + m) * 16))[qtr];
        else            b0 = make_float4(0.f, 0.f, 0.f, 0.f);
        float* bd = sBas + m * 17 + qtr * 4;
        bd[0] = b0.x; bd[1] = b0.y; bd[2] = b0.z; bd[3] = b0.w;
    }
    __syncthreads();

    // coalesced fragment bases (indexed by wn)
    const unsigned* pW1h = g_W1v_hi + wn * 512 + lane * 4;   // per-ks stride 2048
    const unsigned* pW1l = g_W1v_lo + wn * 512 + lane * 4;
    const unsigned* pW2  = g_W2f   + wn * 512 + lane * 4;    // per-t stride 2048

    float acc[2][8][4];
    #pragma unroll
    for (int mt = 0; mt < 2; mt++)
        #pragma unroll
        for (int nt = 0; nt < 8; nt++)
            #pragma unroll
            for (int e = 0; e < 4; e++) acc[mt][nt][e] = 0.f;

    // ========== GEMM1: pre = inter @ W1 (M=64 split 2x32, N=256, K=128), bf16x3, nt=8 ======
    #pragma unroll 1
    for (int ks = 0; ks < 8; ks++) {
        const unsigned* bh = pW1h + ks * 2048;
        const unsigned* bl = pW1l + ks * 2048;
        uint4 H0 = *(const uint4*)(bh),       H1 = *(const uint4*)(bh + 128);
        uint4 H2 = *(const uint4*)(bh + 256), H3 = *(const uint4*)(bh + 384);
        uint4 L0 = *(const uint4*)(bl),       L1 = *(const uint4*)(bl + 128);
        uint4 L2 = *(const uint4*)(bl + 256), L3 = *(const uint4*)(bl + 384);
        const unsigned BH[8][2] = {{H0.x, H0.y}, {H0.z, H0.w}, {H1.x, H1.y}, {H1.z, H1.w},
                                   {H2.x, H2.y}, {H2.z, H2.w}, {H3.x, H3.y}, {H3.z, H3.w}};
        const unsigned BL[8][2] = {{L0.x, L0.y}, {L0.z, L0.w}, {L1.x, L1.y}, {L1.z, L1.w},
                                   {L2.x, L2.y}, {L2.z, L2.w}, {L3.x, L3.y}, {L3.z, L3.w}};
        #pragma unroll
        for (int mt = 0; mt < 2; mt++) {
            unsigned ahi[4], alo[4];
            ldm4(ahi, aHiB + (uint32_t)(((wm * 2 + mt) * 8 + ks) * 512));
            ldm4(alo, aLoB + (uint32_t)(((wm * 2 + mt) * 8 + ks) * 512));
            #pragma unroll
            for (int nt = 0; nt < 8; nt++) {
                mma4(acc[mt][nt], ahi, BH[nt][0], BH[nt][1]);
                mma4(acc[mt][nt], ahi, BL[nt][0], BL[nt][1]);
                mma4(acc[mt][nt], alo, BH[nt][0], BH[nt][1]);
            }
        }
    }
    __syncthreads();  // all inter reads complete before h overwrites the tile region

    // ---- tanh + fp16 convert + store h tiles (idx = (wm*2+mt)*16 + wn*4 + (nt>>1)) ----
    #pragma unroll
    for (int mt = 0; mt < 2; mt++) {
        #pragma unroll
        for (int nt = 0; nt < 8; nt++) {
            const uint32_t tb = (uint32_t)(((wm * 2 + mt) * 16 + wn * 4 + (nt >> 1)) * 512);
            const uint32_t inb = (uint32_t)((nt & 1) * 16 + q * 4);
            unsigned v = h2pk(tanhf(acc[mt][nt][0]), tanhf(acc[mt][nt][1]));
            uint32_t o = (uint32_t)((r * 32 + inb) ^ ((r & 4) << 2));
            sts32(su + OFF_AHI + tb + o, v);
            v = h2pk(tanhf(acc[mt][nt][2]), tanhf(acc[mt][nt][3]));
            const int r1 = r + 8;
            o = (uint32_t)((r1 * 32 + inb) ^ ((r1 & 4) << 2));
            sts32(su + OFF_AHI + tb + o, v);
        }
    }
    #pragma unroll
    for (int mt = 0; mt < 2; mt++)
        #pragma unroll
        for (int nt = 0; nt < 8; nt++)
            #pragma unroll
            for (int e = 0; e < 4; e++) acc[mt][nt][e] = 0.f;
    __syncthreads();

    // ====== GEMM2 fp16 (M=64 split 2x32, N=2048: 8 passes x 16 ksteps, nt=8) ======
    // B double-buffered (D->N), A fragments double-buffered across kc (abuf).
    const uint32_t aBase = aHiB + (uint32_t)(wm * 2 * 16 * 512);
    uint4 D0 = *(const uint4*)(pW2),       D1 = *(const uint4*)(pW2 + 128);
    uint4 D2 = *(const uint4*)(pW2 + 256), D3 = *(const uint4*)(pW2 + 384);
    unsigned abuf[2][2][4];
    #pragma unroll
    for (int mt = 0; mt < 2; mt++)
        ldm4(abuf[0][mt], aBase + (uint32_t)((mt * 16 + 0) * 512));

    #pragma unroll 1
    for (int t = 0; t < 128; t++) {
        const int kc = t & 15;
        const int cur = t & 1, nxt = cur ^ 1;
        // prefetch next B (wraps harmlessly to t=0 at the end)
        const unsigned* np = pW2 + (size_t)((t < 127) ? (t + 1) : 0) * 2048;
        uint4 N0 = *(const uint4*)(np),       N1 = *(const uint4*)(np + 128);
        uint4 N2 = *(const uint4*)(np + 256), N3 = *(const uint4*)(np + 384);
        // prefetch next A fragments (A tiles depend only on kc mod 16)
        const int kn = (kc + 1) & 15;
        #pragma unroll
        for (int mt = 0; mt < 2; mt++)
            ldm4(abuf[nxt][mt], aBase + (uint32_t)((mt * 16 + kn) * 512));
        const unsigned BH[8][2] = {{D0.x, D0.y}, {D0.z, D0.w}, {D1.x, D1.y}, {D1.z, D1.w},
                                   {D2.x, D2.y}, {D2.z, D2.w}, {D3.x, D3.y}, {D3.z, D3.w}};
        #pragma unroll
        for (int mt = 0; mt < 2; mt++)
            #pragma unroll
            for (int nt = 0; nt < 8; nt++)
                mma4h(acc[mt][nt], abuf[cur][mt], BH[nt][0], BH[nt][1]);
        D0 = N0; D1 = N1; D2 = N2; D3 = N3;

        if (kc == 15) {
            const int pass = t >> 4;
            // epilogue: out[m][c] = sum_b H[m][16c+b]*basis[m][b]; warp owns 4 cols/pass
            #pragma unroll
            for (int mt = 0; mt < 2; mt++) {
                const int row0 = wm * 32 + mt * 16 + r, row1 = row0 + 8;
                float b00 = sBas[row0 * 17 + 2 * q],     b01 = sBas[row0 * 17 + 2 * q + 1];
                float b08 = sBas[row0 * 17 + 8 + 2 * q], b09 = sBas[row0 * 17 + 9 + 2 * q];
                float b10 = sBas[row1 * 17 + 2 * q],     b11 = sBas[row1 * 17 + 2 * q + 1];
                float b18 = sBas[row1 * 17 + 8 + 2 * q], b19 = sBas[row1 * 17 + 9 + 2 * q];
                #pragma unroll
                for (int tp = 0; tp < 4; tp++) {
                    float s0 = acc[mt][2 * tp][0] * b00 + acc[mt][2 * tp][1] * b01
                             + acc[mt][2 * tp + 1][0] * b08 + acc[mt][2 * tp + 1][1] * b09;
                    float s1 = acc[mt][2 * tp][2] * b10 + acc[mt][2 * tp][3] * b11
                             + acc[mt][2 * tp + 1][2] * b18 + acc[mt][2 * tp + 1][3] * b19;
                    s0 += __shfl_xor_sync(0xffffffffu, s0, 1);
                    s0 += __shfl_xor_sync(0xffffffffu, s0, 2);
                    s1 += __shfl_xor_sync(0xffffffffu, s1, 1);
                    s1 += __shfl_xor_sync(0xffffffffu, s1, 2);
                    if (q == 0) {
                        const int c = pass * 16 + wn * 4 + tp;
                        sOut[row0 * 132 + c] = s0;
                        sOut[row1 * 132 + c] = s1;
                    }
                }
                #pragma unroll
                for (int nt = 0; nt < 8; nt++)
                    #pragma unroll
                    for (int e = 0; e < 4; e++) acc[mt][nt][e] = 0.f;
            }
        }
    }
    __syncthreads();

    // ---- coalesced output store ----
    #pragma unroll 1
    for (int i = tid; i < TM * 32; i += 256) {
        const int m = i >> 5, c4 = i & 31;
        if (m < mvalid) {
            const float4 v = *(const float4*)(sOut + m * 132 + c4 * 4);
            *(float4*)(out + ((size_t)(m0 + m)) * NIN + c4 * 4) = v;
        }
    }
}

extern "C" void kernel_launch(void* const* d_in, const int* in_sizes, int n_in,
                              void* d_out, int out_size) {
    const float* prop  = (const float*)d_in[0];
    const void*  idxi  = d_in[1];
    const void*  idxj  = d_in[2];
    const float* basis = (const float*)d_in[3];
    const float* W1    = (const float*)d_in[4];
    const float* W2    = (const float*)d_in[5];
    float* out = (float*)d_out;
    const int P = out_size / NIN;
    (void)in_sizes; (void)n_in;

    cudaFuncSetAttribute(pilayer_kernel, cudaFuncAttributeMaxDynamicSharedMemorySize, SMEM_BYTES);

    detect_idx_kernel<<<1, 32>>>((const unsigned*)idxi);
    prep_w1_kernel<<<64, 256>>>(W1);
    prep_w2_kernel<<<1024, 256>>>(W2);

    const int blocks = (P + TM - 1) / TM;
    pilayer_kernel<<<blocks, 256, SMEM_BYTES>>>(prop, idxi, idxj, basis, out, P);
}

// round 16
// speedup vs baseline: 1.5903x; 1.5903x over previous
#include <cuda_runtime.h>
#include <cuda_bf16.h>
#include <cuda_fp16.h>
#include <cstdint>

#define NIN 128
#define TM  64

// ---- SMEM map (bytes), per CTA (2 CTAs/SM) ----
// GEMM1 A (inter): bf16 16x16 tiles, 512B, idx = mt*8 + kc (32 tiles/half)
// GEMM2 A (h): fp16 16x16 tiles, 512B, idx = mtile*16 + kc (64 tiles, 32KB), overwrites inter
#define OFF_AHI 0
#define OFF_ALO 32768
#define OFF_BAS 65536                 // 64 * 17 * 4 = 4352
#define OFF_OUT 69888                 // 64 * 132 * 4 = 33792
#define SMEM_BYTES 103680

// ---- device scratch: fragment-ordered weights (coalesced 512B warp spans) ----
// W1 hi/lo: [ks(8)][wn(4)][g(4)][lane(32)][word(4)]  (16384 words each, bf16 pairs)
// W2 fp16 : [t(128)][wn(4)][g(4)][lane(32)][word(4)] (262144 words, fp16 pairs)
__device__ __align__(16) unsigned g_W1v_hi[16384];
__device__ __align__(16) unsigned g_W1v_lo[16384];
__device__ __align__(16) unsigned g_W2f[262144];
__device__ int g_idx64;

// -------- helpers --------
__device__ __forceinline__ uint32_t smem_u32(const void* p) {
    uint32_t a;
    asm("{ .reg .u64 t; cvta.to.shared.u64 t, %1; cvt.u32.u64 %0, t; }" : "=r"(a) : "l"(p));
    return a;
}
__device__ __forceinline__ unsigned pk(float x0, float x1, unsigned& lo) {
    __nv_bfloat16 h0 = __float2bfloat16(x0), h1 = __float2bfloat16(x1);
    float r0 = x0 - __bfloat162float(h0);
    float r1 = x1 - __bfloat162float(h1);
    __nv_bfloat16 l0 = __float2bfloat16(r0), l1 = __float2bfloat16(r1);
    lo = ((unsigned)__bfloat16_as_ushort(l1) << 16) | (unsigned)__bfloat16_as_ushort(l0);
    return ((unsigned)__bfloat16_as_ushort(h1) << 16) | (unsigned)__bfloat16_as_ushort(h0);
}
__device__ __forceinline__ unsigned h2pk(float x0, float x1) {   // x0 -> low half
    unsigned u;
    asm("cvt.rn.f16x2.f32 %0, %1, %2;" : "=r"(u) : "f"(x1), "f"(x0));
    return u;
}
__device__ __forceinline__ void st128s(uint32_t a, unsigned x, unsigned y, unsigned z, unsigned w) {
    asm volatile("st.shared.v4.b32 [%0], {%1,%2,%3,%4};" :: "r"(a), "r"(x), "r"(y), "r"(z), "r"(w) : "memory");
}
__device__ __forceinline__ void sts32(uint32_t a, unsigned v) {
    asm volatile("st.shared.b32 [%0], %1;" :: "r"(a), "r"(v) : "memory");
}
__device__ __forceinline__ void ldm4(unsigned (&a)[4], uint32_t addr) {
    asm volatile("ldmatrix.sync.aligned.m8n8.x4.shared.b16 {%0,%1,%2,%3}, [%4];"
                 : "=r"(a[0]), "=r"(a[1]), "=r"(a[2]), "=r"(a[3]) : "r"(addr));
}
__device__ __forceinline__ void mma4(float (&d)[4], const unsigned (&a)[4], unsigned b0, unsigned b1) {
    asm volatile(
        "mma.sync.aligned.m16n8k16.row.col.f32.bf16.bf16.f32 "
        "{%0,%1,%2,%3},{%4,%5,%6,%7},{%8,%9},{%0,%1,%2,%3};\n"
        : "+f"(d[0]), "+f"(d[1]), "+f"(d[2]), "+f"(d[3])
        : "r"(a[0]), "r"(a[1]), "r"(a[2]), "r"(a[3]), "r"(b0), "r"(b1));
}
__device__ __forceinline__ void mma4h(float (&d)[4], const unsigned (&a)[4], unsigned b0, unsigned b1) {
    asm volatile(
        "mma.sync.aligned.m16n8k16.row.col.f32.f16.f16.f32 "
        "{%0,%1,%2,%3},{%4,%5,%6,%7},{%8,%9},{%0,%1,%2,%3};\n"
        : "+f"(d[0]), "+f"(d[1]), "+f"(d[2]), "+f"(d[3])
        : "r"(a[0]), "r"(a[1]), "r"(a[2]), "r"(a[3]), "r"(b0), "r"(b1));
}

// -------- prep kernels --------
__global__ void detect_idx_kernel(const unsigned* __restrict__ idx_raw) {
    if (threadIdx.x == 0) {
        unsigned nz = 0;
        #pragma unroll 1
        for (int k = 0; k < 64; k++) nz |= idx_raw[2 * k + 1];
        g_idx64 = (nz == 0) ? 1 : 0;  // int64 values < 2^31 -> high words all zero
    }
}

// W1 [128,256] -> [ks(8)][wn(4)][g(4)][lane][word]; e = g*4+word; nt = e>>1; khalf = e&1
__global__ void prep_w1_kernel(const float* __restrict__ W1) {
    int i = blockIdx.x * 256 + threadIdx.x;        // 16384
    int word = i & 3, lane = (i >> 2) & 31, g = (i >> 7) & 3, wn = (i >> 9) & 3, ks = i >> 11;
    int q = lane & 3, r = lane >> 2;
    int e = g * 4 + word;
    int nt = e >> 1, khalf = e & 1;
    int kpair = ks * 8 + khalf * 4 + q;
    int col = wn * 64 + nt * 8 + r;
    float x0 = W1[(2 * kpair) * 256 + col];
    float x1 = W1[(2 * kpair + 1) * 256 + col];
    unsigned lo, hi = pk(x0, x1, lo);
    g_W1v_hi[i] = hi; g_W1v_lo[i] = lo;
}

// W2 [256,2048] -> fp16 pairs [t(128)][wn(4)][g(4)][lane][word]; e = g*4+word
// t = pass*16 + kstep; nt = e>>1; khalf = e&1; k = kstep*16 + khalf*8 + 2q; col = pass*256 + wn*64 + nt*8 + r
__global__ void prep_w2_kernel(const float* __restrict__ W2) {
    int i = blockIdx.x * 256 + threadIdx.x;        // 262144
    int word = i & 3, lane = (i >> 2) & 31, g = (i >> 7) & 3, wn = (i >> 9) & 3, t = i >> 11;
    int q = lane & 3, r = lane >> 2;
    int e = g * 4 + word;
    int nt = e >> 1, khalf = e & 1;
    int kstep = t & 15, pass = t >> 4;
    int k = kstep * 16 + khalf * 8 + 2 * q;
    int col = pass * 256 + wn * 64 + nt * 8 + r;
    g_W2f[i] = h2pk(W2[k * 2048 + col], W2[(k + 1) * 2048 + col]);
}

// -------- main kernel: 256 threads (8 warps, M2 x N4 split), TM=64, 2 CTAs/SM --------
__global__ void __launch_bounds__(256, 2) pilayer_kernel(
    const float* __restrict__ prop, const void* __restrict__ idxi_raw,
    const void* __restrict__ idxj_raw, const float* __restrict__ basis,
    float* __restrict__ out, int P)
{
    extern __shared__ __align__(1024) char smem[];
    const uint32_t su = smem_u32(smem);
    float* sBas = (float*)(smem + OFF_BAS);
    float* sOut = (float*)(smem + OFF_OUT);

    const int tid = threadIdx.x;
    const int w = tid >> 5, lane = tid & 31, q = lane & 3, r = lane >> 2;
    const int wm = w >> 2, wn = w & 3;
    const int m0 = blockIdx.x * TM;
    const int mvalid = min(TM, P - m0);
    const bool is64 = (g_idx64 != 0);

    // per-lane ldmatrix offset within a 512B (16 rows x 32B) tile
    const int rL = (lane & 7) + (lane & 8);
    const int hL = lane >> 4;
    const uint32_t lmoff = (uint32_t)((rL * 32 + hL * 16) ^ ((rL & 4) << 2));
    const uint32_t aHiB = su + OFF_AHI + lmoff;
    const uint32_t aLoB = su + OFF_ALO + lmoff;

    // ---- gather: inter = prop[idx_i] + prop[idx_j]; bf16 hi/lo split, swizzled tiles ----
    {
        const int m = tid >> 2, qtr = tid & 3;     // 4 threads per row, 32 k-cols each
        const int mt = m >> 4, rr = m & 15;
        const unsigned swz = (unsigned)((rr & 4) << 2);
        const uint32_t o0 = (uint32_t)((rr * 32) ^ swz);
        const uint32_t o1 = o0 ^ 16u;
        if (m < mvalid) {
            long long e = (long long)(m0 + m);
            long long ia, ja;
            if (is64) { ia = ((const long long*)idxi_raw)[e]; ja = ((const long long*)idxj_raw)[e]; }
            else      { ia = ((const int*)idxi_raw)[e];       ja = ((const int*)idxj_raw)[e]; }
            const float4* pi = (const float4*)(prop + ia * NIN);
            const float4* pj = (const float4*)(prop + ja * NIN);
            #pragma unroll
            for (int kc = 0; kc < 2; kc++) {
                const int kcg = qtr * 2 + kc;
                const uint32_t tb = (uint32_t)((mt * 8 + kcg) * 512);
                float4 A0 = pi[kcg * 4], A1 = pi[kcg * 4 + 1], A2 = pi[kcg * 4 + 2], A3 = pi[kcg * 4 + 3];
                float4 B0 = pj[kcg * 4], B1 = pj[kcg * 4 + 1], B2 = pj[kcg * 4 + 2], B3 = pj[kcg * 4 + 3];
                unsigned h0, h1, h2, h3, h4, h5, h6, h7, l0, l1, l2, l3, l4, l5, l6, l7;
                h0 = pk(A0.x + B0.x, A0.y + B0.y, l0);
                h1 = pk(A0.z + B0.z, A0.w + B0.w, l1);
                h2 = pk(A1.x + B1.x, A1.y + B1.y, l2);
                h3 = pk(A1.z + B1.z, A1.w + B1.w, l3);
                h4 = pk(A2.x + B2.x, A2.y + B2.y, l4);
                h5 = pk(A2.z + B2.z, A2.w + B2.w, l5);
                h6 = pk(A3.x + B3.x, A3.y + B3.y, l6);
                h7 = pk(A3.z + B3.z, A3.w + B3.w, l7);
                st128s(su + OFF_AHI + tb + o0, h0, h1, h2, h3);
                st128s(su + OFF_AHI + tb + o1, h4, h5, h6, h7);
                st128s(su + OFF_ALO + tb + o0, l0, l1, l2, l3);
                st128s(su + OFF_ALO + tb + o1, l4, l5, l6, l7);
            }
        } else {
            #pragma unroll
            for (int kc = 0; kc < 2; kc++) {
                const uint32_t tb = (uint32_t)((mt * 8 + qtr * 2 + kc) * 512);
                st128s(su + OFF_AHI + tb + o0, 0, 0, 0, 0);
                st128s(su + OFF_AHI + tb + o1, 0, 0, 0, 0);
                st128s(su + OFF_ALO + tb + o0, 0, 0, 0, 0);
                st128s(su + OFF_ALO + tb + o1, 0, 0, 0, 0);
            }
        }
        // basis rows (zero-padded past mvalid): each thread one float4
        float4 b0;
        if (m < mvalid) b0 = ((const float4*)(basis + (size_t)(m0 + m) * 16))[qtr];
        else            b0 = make_float4(0.f, 0.f, 0.f, 0.f);
        float* bd = sBas + m * 17 + qtr * 4;
        bd[0] = b0.x; bd[1] = b0.y; bd[2] = b0.z; bd[3] = b0.w;
    }
    __syncthreads();

    // coalesced fragment bases (indexed by wn)
    const unsigned* pW1h = g_W1v_hi + wn * 512 + lane * 4;   // per-ks stride 2048
    const unsigned* pW1l = g_W1v_lo + wn * 512 + lane * 4;
    const unsigned* pW2  = g_W2f   + wn * 512 + lane * 4;    // per-t stride 2048

    float acc[2][8][4];
    #pragma unroll
    for (int mt = 0; mt < 2; mt++)
        #pragma unroll
        for (int nt = 0; nt < 8; nt++)
            #pragma unroll
            for (int e = 0; e < 4; e++) acc[mt][nt][e] = 0.f;

    // ========== GEMM1: pre = inter @ W1 (M=64 split 2x32, N=256, K=128), bf16x3, nt=8 ======
    #pragma unroll 1
    for (int ks = 0; ks < 8; ks++) {
        const unsigned* bh = pW1h + ks * 2048;
        const unsigned* bl = pW1l + ks * 2048;
        uint4 H0 = *(const uint4*)(bh),       H1 = *(const uint4*)(bh + 128);
        uint4 H2 = *(const uint4*)(bh + 256), H3 = *(const uint4*)(bh + 384);
        uint4 L0 = *(const uint4*)(bl),       L1 = *(const uint4*)(bl + 128);
        uint4 L2 = *(const uint4*)(bl + 256), L3 = *(const uint4*)(bl + 384);
        const unsigned BH[8][2] = {{H0.x, H0.y}, {H0.z, H0.w}, {H1.x, H1.y}, {H1.z, H1.w},
                                   {H2.x, H2.y}, {H2.z, H2.w}, {H3.x, H3.y}, {H3.z, H3.w}};
        const unsigned BL[8][2] = {{L0.x, L0.y}, {L0.z, L0.w}, {L1.x, L1.y}, {L1.z, L1.w},
                                   {L2.x, L2.y}, {L2.z, L2.w}, {L3.x, L3.y}, {L3.z, L3.w}};
        #pragma unroll
        for (int mt = 0; mt < 2; mt++) {
            unsigned ahi[4], alo[4];
            ldm4(ahi, aHiB + (uint32_t)(((wm * 2 + mt) * 8 + ks) * 512));
            ldm4(alo, aLoB + (uint32_t)(((wm * 2 + mt) * 8 + ks) * 512));
            #pragma unroll
            for (int nt = 0; nt < 8; nt++) {
                mma4(acc[mt][nt], ahi, BH[nt][0], BH[nt][1]);
                mma4(acc[mt][nt], ahi, BL[nt][0], BL[nt][1]);
                mma4(acc[mt][nt], alo, BH[nt][0], BH[nt][1]);
            }
        }
    }
    __syncthreads();  // all inter reads complete before h overwrites the tile region

    // ---- tanh + fp16 convert + store h tiles (idx = (wm*2+mt)*16 + wn*4 + (nt>>1)) ----
    #pragma unroll
    for (int mt = 0; mt < 2; mt++) {
        #pragma unroll
        for (int nt = 0; nt < 8; nt++) {
            const uint32_t tb = (uint32_t)(((wm * 2 + mt) * 16 + wn * 4 + (nt >> 1)) * 512);
            const uint32_t inb = (uint32_t)((nt & 1) * 16 + q * 4);
            unsigned v = h2pk(tanhf(acc[mt][nt][0]), tanhf(acc[mt][nt][1]));
            uint32_t o = (uint32_t)((r * 32 + inb) ^ ((r & 4) << 2));
            sts32(su + OFF_AHI + tb + o, v);
            v = h2pk(tanhf(acc[mt][nt][2]), tanhf(acc[mt][nt][3]));
            const int r1 = r + 8;
            o = (uint32_t)((r1 * 32 + inb) ^ ((r1 & 4) << 2));
            sts32(su + OFF_AHI + tb + o, v);
        }
    }
    #pragma unroll
    for (int mt = 0; mt < 2; mt++)
        #pragma unroll
        for (int nt = 0; nt < 8; nt++)
            #pragma unroll
            for (int e = 0; e < 4; e++) acc[mt][nt][e] = 0.f;
    __syncthreads();

    // ====== GEMM2 fp16 (M=64 split 2x32, 8 passes x 16 ksteps, nt=8) ======
    // B double-buffered (D->N). Epilogue hoisted out of the kc loop.
    const uint32_t aBase = aHiB + (uint32_t)(wm * 2 * 16 * 512);
    uint4 D0 = *(const uint4*)(pW2),       D1 = *(const uint4*)(pW2 + 128);
    uint4 D2 = *(const uint4*)(pW2 + 256), D3 = *(const uint4*)(pW2 + 384);

    #pragma unroll 1
    for (int pass = 0; pass < 8; pass++) {
        #pragma unroll 2
        for (int kc = 0; kc < 16; kc++) {
            const int t = pass * 16 + kc;
            const unsigned* np = pW2 + (size_t)((t < 127) ? (t + 1) : 0) * 2048;
            uint4 N0 = *(const uint4*)(np),       N1 = *(const uint4*)(np + 128);
            uint4 N2 = *(const uint4*)(np + 256), N3 = *(const uint4*)(np + 384);
            const unsigned BH[8][2] = {{D0.x, D0.y}, {D0.z, D0.w}, {D1.x, D1.y}, {D1.z, D1.w},
                                       {D2.x, D2.y}, {D2.z, D2.w}, {D3.x, D3.y}, {D3.z, D3.w}};
            #pragma unroll
            for (int mt = 0; mt < 2; mt++) {
                unsigned a[4];
                ldm4(a, aBase + (uint32_t)((mt * 16 + kc) * 512));
                #pragma unroll
                for (int nt = 0; nt < 8; nt++)
                    mma4h(acc[mt][nt], a, BH[nt][0], BH[nt][1]);
            }
            D0 = N0; D1 = N1; D2 = N2; D3 = N3;
        }
        // epilogue: out[m][c] = sum_b H[m][16c+b]*basis[m][b]; warp owns 4 cols/pass
        #pragma unroll
        for (int mt = 0; mt < 2; mt++) {
            const int row0 = wm * 32 + mt * 16 + r, row1 = row0 + 8;
            float b00 = sBas[row0 * 17 + 2 * q],     b01 = sBas[row0 * 17 + 2 * q + 1];
            float b08 = sBas[row0 * 17 + 8 + 2 * q], b09 = sBas[row0 * 17 + 9 + 2 * q];
            float b10 = sBas[row1 * 17 + 2 * q],     b11 = sBas[row1 * 17 + 2 * q + 1];
            float b18 = sBas[row1 * 17 + 8 + 2 * q], b19 = sBas[row1 * 17 + 9 + 2 * q];
            #pragma unroll
            for (int tp = 0; tp < 4; tp++) {
                float s0 = acc[mt][2 * tp][0] * b00 + acc[mt][2 * tp][1] * b01
                         + acc[mt][2 * tp + 1][0] * b08 + acc[mt][2 * tp + 1][1] * b09;
                float s1 = acc[mt][2 * tp][2] * b10 + acc[mt][2 * tp][3] * b11
                         + acc[mt][2 * tp + 1][2] * b18 + acc[mt][2 * tp + 1][3] * b19;
                s0 += __shfl_xor_sync(0xffffffffu, s0, 1);
                s0 += __shfl_xor_sync(0xffffffffu, s0, 2);
                s1 += __shfl_xor_sync(0xffffffffu, s1, 1);
                s1 += __shfl_xor_sync(0xffffffffu, s1, 2);
                if (q == 0) {
                    const int c = pass * 16 + wn * 4 + tp;
                    sOut[row0 * 132 + c] = s0;
                    sOut[row1 * 132 + c] = s1;
                }
            }
            #pragma unroll
            for (int nt = 0; nt < 8; nt++)
                #pragma unroll
                for (int e = 0; e < 4; e++) acc[mt][nt][e] = 0.f;
        }
    }
    __syncthreads();

    // ---- coalesced output store ----
    #pragma unroll 1
    for (int i = tid; i < TM * 32; i += 256) {
        const int m = i >> 5, c4 = i & 31;
        if (m < mvalid) {
            const float4 v = *(const float4*)(sOut + m * 132 + c4 * 4);
            *(float4*)(out + ((size_t)(m0 + m)) * NIN + c4 * 4) = v;
        }
    }
}

extern "C" void kernel_launch(void* const* d_in, const int* in_sizes, int n_in,
                              void* d_out, int out_size) {
    const float* prop  = (const float*)d_in[0];
    const void*  idxi  = d_in[1];
    const void*  idxj  = d_in[2];
    const float* basis = (const float*)d_in[3];
    const float* W1    = (const float*)d_in[4];
    const float* W2    = (const float*)d_in[5];
    float* out = (float*)d_out;
    const int P = out_size / NIN;
    (void)in_sizes; (void)n_in;

    cudaFuncSetAttribute(pilayer_kernel, cudaFuncAttributeMaxDynamicSharedMemorySize, SMEM_BYTES);

    detect_idx_kernel<<<1, 32>>>((const unsigned*)idxi);
    prep_w1_kernel<<<64, 256>>>(W1);
    prep_w2_kernel<<<1024, 256>>>(W2);

    const int blocks = (P + TM - 1) / TM;
    pilayer_kernel<<<blocks, 256, SMEM_BYTES>>>(prop, idxi, idxj, basis, out, P);
}

// round 17
// speedup vs baseline: 1.6941x; 1.0653x over previous
#include <cuda_runtime.h>
#include <cuda_bf16.h>
#include <cuda_fp16.h>
#include <cstdint>

#define NIN 128
#define TM  64

// ---- hot-kernel SMEM map (bytes) ----
// h tiles: fp16 16x16 (512B), idx = (m/16)*16 + (hcol/16)  (64 tiles, 32KB)
#define OFF_H   0
#define OFF_BAS 32768                 // 64 * 17 * 4 = 4352
#define OFF_OUT 37120                 // 64 * 132 * 4 = 33792
#define SMEM_BYTES 70912
// prep_u SMEM: bf16 hi/lo tile regions (32KB each)
#define SMEM_PREP 65536

// ---- device scratch ----
// W1 hi/lo: [ks(8)][wn(4)][g(4)][lane(32)][word(4)]  (bf16 pairs)
// W2 fp16 : [t(128)][wn(4)][g(4)][lane(32)][word(4)] (fp16 pairs)
// U = prop @ W1 (fp32), [50000+pad, 256]
__device__ __align__(16) unsigned g_W1v_hi[16384];
__device__ __align__(16) unsigned g_W1v_lo[16384];
__device__ __align__(16) unsigned g_W2f[262144];
__device__ __align__(16) float g_U[50048 * 256];
__device__ int g_idx64;

// -------- helpers --------
__device__ __forceinline__ uint32_t smem_u32(const void* p) {
    uint32_t a;
    asm("{ .reg .u64 t; cvta.to.shared.u64 t, %1; cvt.u32.u64 %0, t; }" : "=r"(a) : "l"(p));
    return a;
}
__device__ __forceinline__ unsigned pk(float x0, float x1, unsigned& lo) {
    __nv_bfloat16 h0 = __float2bfloat16(x0), h1 = __float2bfloat16(x1);
    float r0 = x0 - __bfloat162float(h0);
    float r1 = x1 - __bfloat162float(h1);
    __nv_bfloat16 l0 = __float2bfloat16(r0), l1 = __float2bfloat16(r1);
    lo = ((unsigned)__bfloat16_as_ushort(l1) << 16) | (unsigned)__bfloat16_as_ushort(l0);
    return ((unsigned)__bfloat16_as_ushort(h1) << 16) | (unsigned)__bfloat16_as_ushort(h0);
}
__device__ __forceinline__ unsigned h2pk(float x0, float x1) {   // x0 -> low half
    unsigned u;
    asm("cvt.rn.f16x2.f32 %0, %1, %2;" : "=r"(u) : "f"(x1), "f"(x0));
    return u;
}
__device__ __forceinline__ void st128s(uint32_t a, unsigned x, unsigned y, unsigned z, unsigned w) {
    asm volatile("st.shared.v4.b32 [%0], {%1,%2,%3,%4};" :: "r"(a), "r"(x), "r"(y), "r"(z), "r"(w) : "memory");
}
__device__ __forceinline__ void ldm4(unsigned (&a)[4], uint32_t addr) {
    asm volatile("ldmatrix.sync.aligned.m8n8.x4.shared.b16 {%0,%1,%2,%3}, [%4];"
                 : "=r"(a[0]), "=r"(a[1]), "=r"(a[2]), "=r"(a[3]) : "r"(addr));
}
__device__ __forceinline__ void mma4(float (&d)[4], const unsigned (&a)[4], unsigned b0, unsigned b1) {
    asm volatile(
        "mma.sync.aligned.m16n8k16.row.col.f32.bf16.bf16.f32 "
        "{%0,%1,%2,%3},{%4,%5,%6,%7},{%8,%9},{%0,%1,%2,%3};\n"
        : "+f"(d[0]), "+f"(d[1]), "+f"(d[2]), "+f"(d[3])
        : "r"(a[0]), "r"(a[1]), "r"(a[2]), "r"(a[3]), "r"(b0), "r"(b1));
}
__device__ __forceinline__ void mma4h(float (&d)[4], const unsigned (&a)[4], unsigned b0, unsigned b1) {
    asm volatile(
        "mma.sync.aligned.m16n8k16.row.col.f32.f16.f16.f32 "
        "{%0,%1,%2,%3},{%4,%5,%6,%7},{%8,%9},{%0,%1,%2,%3};\n"
        : "+f"(d[0]), "+f"(d[1]), "+f"(d[2]), "+f"(d[3])
        : "r"(a[0]), "r"(a[1]), "r"(a[2]), "r"(a[3]), "r"(b0), "r"(b1));
}

// -------- prep kernels --------
__global__ void detect_idx_kernel(const unsigned* __restrict__ idx_raw) {
    if (threadIdx.x == 0) {
        unsigned nz = 0;
        #pragma unroll 1
        for (int k = 0; k < 64; k++) nz |= idx_raw[2 * k + 1];
        g_idx64 = (nz == 0) ? 1 : 0;  // int64 values < 2^31 -> high words all zero
    }
}

// W1 [128,256] -> [ks(8)][wn(4)][g(4)][lane][word]; e = g*4+word; nt = e>>1; khalf = e&1
__global__ void prep_w1_kernel(const float* __restrict__ W1) {
    int i = blockIdx.x * 256 + threadIdx.x;        // 16384
    int word = i & 3, lane = (i >> 2) & 31, g = (i >> 7) & 3, wn = (i >> 9) & 3, ks = i >> 11;
    int q = lane & 3, r = lane >> 2;
    int e = g * 4 + word;
    int nt = e >> 1, khalf = e & 1;
    int kpair = ks * 8 + khalf * 4 + q;
    int col = wn * 64 + nt * 8 + r;
    float x0 = W1[(2 * kpair) * 256 + col];
    float x1 = W1[(2 * kpair + 1) * 256 + col];
    unsigned lo, hi = pk(x0, x1, lo);
    g_W1v_hi[i] = hi; g_W1v_lo[i] = lo;
}

// W2 [256,2048] -> fp16 pairs [t(128)][wn(4)][g(4)][lane][word]
__global__ void prep_w2_kernel(const float* __restrict__ W2) {
    int i = blockIdx.x * 256 + threadIdx.x;        // 262144
    int word = i & 3, lane = (i >> 2) & 31, g = (i >> 7) & 3, wn = (i >> 9) & 3, t = i >> 11;
    int q = lane & 3, r = lane >> 2;
    int e = g * 4 + word;
    int nt = e >> 1, khalf = e & 1;
    int kstep = t & 15, pass = t >> 4;
    int k = kstep * 16 + khalf * 8 + 2 * q;
    int col = pass * 256 + wn * 64 + nt * 8 + r;
    g_W2f[i] = h2pk(W2[k * 2048 + col], W2[(k + 1) * 2048 + col]);
}

// -------- prep_u: U = prop @ W1 (bf16x3), 64 nodes per CTA --------
__global__ void __launch_bounds__(256, 2) prep_u_kernel(const float* __restrict__ prop, int NN) {
    extern __shared__ __align__(1024) char smem[];
    const uint32_t su = smem_u32(smem);
    const int tid = threadIdx.x;
    const int w = tid >> 5, lane = tid & 31, q = lane & 3, r = lane >> 2;
    const int wm = w >> 2, wn = w & 3;
    const int n0 = blockIdx.x * TM;
    const int nvalid = min(TM, NN - n0);

    const int rL = (lane & 7) + (lane & 8);
    const int hL = lane >> 4;
    const uint32_t lmoff = (uint32_t)((rL * 32 + hL * 16) ^ ((rL & 4) << 2));
    const uint32_t aHiB = su + 0 + lmoff;
    const uint32_t aLoB = su + 32768 + lmoff;

    // load prop rows -> bf16 hi/lo split swizzled tiles
    {
        const int m = tid >> 2, qtr = tid & 3;
        const int mt = m >> 4, rr = m & 15;
        const unsigned swz = (unsigned)((rr & 4) << 2);
        const uint32_t o0 = (uint32_t)((rr * 32) ^ swz);
        const uint32_t o1 = o0 ^ 16u;
        if (m < nvalid) {
            const float4* pi = (const float4*)(prop + (size_t)(n0 + m) * NIN);
            #pragma unroll
            for (int kc = 0; kc < 2; kc++) {
                const int kcg = qtr * 2 + kc;
                const uint32_t tb = (uint32_t)((mt * 8 + kcg) * 512);
                float4 A0 = pi[kcg * 4], A1 = pi[kcg * 4 + 1], A2 = pi[kcg * 4 + 2], A3 = pi[kcg * 4 + 3];
                unsigned h0, h1, h2, h3, h4, h5, h6, h7, l0, l1, l2, l3, l4, l5, l6, l7;
                h0 = pk(A0.x, A0.y, l0); h1 = pk(A0.z, A0.w, l1);
                h2 = pk(A1.x, A1.y, l2); h3 = pk(A1.z, A1.w, l3);
                h4 = pk(A2.x, A2.y, l4); h5 = pk(A2.z, A2.w, l5);
                h6 = pk(A3.x, A3.y, l6); h7 = pk(A3.z, A3.w, l7);
                st128s(su + 0 + tb + o0, h0, h1, h2, h3);
                st128s(su + 0 + tb + o1, h4, h5, h6, h7);
                st128s(su + 32768 + tb + o0, l0, l1, l2, l3);
                st128s(su + 32768 + tb + o1, l4, l5, l6, l7);
            }
        } else {
            #pragma unroll
            for (int kc = 0; kc < 2; kc++) {
                const uint32_t tb = (uint32_t)((mt * 8 + qtr * 2 + kc) * 512);
                st128s(su + 0 + tb + o0, 0, 0, 0, 0);
                st128s(su + 0 + tb + o1, 0, 0, 0, 0);
                st128s(su + 32768 + tb + o0, 0, 0, 0, 0);
                st128s(su + 32768 + tb + o1, 0, 0, 0, 0);
            }
        }
    }
    __syncthreads();

    const unsigned* pW1h = g_W1v_hi + wn * 512 + lane * 4;
    const unsigned* pW1l = g_W1v_lo + wn * 512 + lane * 4;

    float acc[2][8][4];
    #pragma unroll
    for (int mt = 0; mt < 2; mt++)
        #pragma unroll
        for (int nt = 0; nt < 8; nt++)
            #pragma unroll
            for (int e = 0; e < 4; e++) acc[mt][nt][e] = 0.f;

    #pragma unroll 1
    for (int ks = 0; ks < 8; ks++) {
        const unsigned* bh = pW1h + ks * 2048;
        const unsigned* bl = pW1l + ks * 2048;
        uint4 H0 = *(const uint4*)(bh),       H1 = *(const uint4*)(bh + 128);
        uint4 H2 = *(const uint4*)(bh + 256), H3 = *(const uint4*)(bh + 384);
        uint4 L0 = *(const uint4*)(bl),       L1 = *(const uint4*)(bl + 128);
        uint4 L2 = *(const uint4*)(bl + 256), L3 = *(const uint4*)(bl + 384);
        const unsigned BH[8][2] = {{H0.x, H0.y}, {H0.z, H0.w}, {H1.x, H1.y}, {H1.z, H1.w},
                                   {H2.x, H2.y}, {H2.z, H2.w}, {H3.x, H3.y}, {H3.z, H3.w}};
        const unsigned BL[8][2] = {{L0.x, L0.y}, {L0.z, L0.w}, {L1.x, L1.y}, {L1.z, L1.w},
                                   {L2.x, L2.y}, {L2.z, L2.w}, {L3.x, L3.y}, {L3.z, L3.w}};
        #pragma unroll
        for (int mt = 0; mt < 2; mt++) {
            unsigned ahi[4], alo[4];
            ldm4(ahi, aHiB + (uint32_t)(((wm * 2 + mt) * 8 + ks) * 512));
            ldm4(alo, aLoB + (uint32_t)(((wm * 2 + mt) * 8 + ks) * 512));
            #pragma unroll
            for (int nt = 0; nt < 8; nt++) {
                mma4(acc[mt][nt], ahi, BH[nt][0], BH[nt][1]);
                mma4(acc[mt][nt], ahi, BL[nt][0], BL[nt][1]);
                mma4(acc[mt][nt], alo, BH[nt][0], BH[nt][1]);
            }
        }
    }

    // write U (fp32): row = n0 + wm*32 + mt*16 + r(+8), col = wn*64 + nt*8 + 2q
    #pragma unroll
    for (int mt = 0; mt < 2; mt++) {
        const int row0 = wm * 32 + mt * 16 + r, row1 = row0 + 8;
        #pragma unroll
        for (int nt = 0; nt < 8; nt++) {
            const int col = wn * 64 + nt * 8 + 2 * q;
            if (row0 < nvalid)
                *(float2*)(g_U + (size_t)(n0 + row0) * 256 + col) = make_float2(acc[mt][nt][0], acc[mt][nt][1]);
            if (row1 < nvalid)
                *(float2*)(g_U + (size_t)(n0 + row1) * 256 + col) = make_float2(acc[mt][nt][2], acc[mt][nt][3]);
        }
    }
}

// -------- main kernel: 256 threads (8 warps, M2 x N4 split), TM=64, 2 CTAs/SM --------
__global__ void __launch_bounds__(256, 2) pilayer_kernel(
    const void* __restrict__ idxi_raw, const void* __restrict__ idxj_raw,
    const float* __restrict__ basis, float* __restrict__ out, int P)
{
    extern __shared__ __align__(1024) char smem[];
    const uint32_t su = smem_u32(smem);
    float* sBas = (float*)(smem + OFF_BAS);
    float* sOut = (float*)(smem + OFF_OUT);

    const int tid = threadIdx.x;
    const int w = tid >> 5, lane = tid & 31, q = lane & 3, r = lane >> 2;
    const int wm = w >> 2, wn = w & 3;
    const int m0 = blockIdx.x * TM;
    const int mvalid = min(TM, P - m0);
    const bool is64 = (g_idx64 != 0);

    // per-lane ldmatrix offset within a 512B (16 rows x 32B) tile
    const int rL = (lane & 7) + (lane & 8);
    const int hL = lane >> 4;
    const uint32_t lmoff = (uint32_t)((rL * 32 + hL * 16) ^ ((rL & 4) << 2));
    const uint32_t aHB = su + OFF_H + lmoff;

    // ---- phase 1: h = tanh(U[i] + U[j]) -> fp16 swizzled tiles ----
    {
        const int m = tid >> 2, qtr = tid & 3;     // 4 threads/row, 64 hidden cols each
        const int mt = m >> 4, rr = m & 15;
        const unsigned swz = (unsigned)((rr & 4) << 2);
        const uint32_t o0 = (uint32_t)((rr * 32) ^ swz);
        const uint32_t o1 = o0 ^ 16u;
        if (m < mvalid) {
            long long e = (long long)(m0 + m);
            long long ia, ja;
            if (is64) { ia = ((const long long*)idxi_raw)[e]; ja = ((const long long*)idxj_raw)[e]; }
            else      { ia = ((const int*)idxi_raw)[e];       ja = ((const int*)idxj_raw)[e]; }
            const float4* ui = (const float4*)(g_U + ia * 256 + qtr * 64);
            const float4* uj = (const float4*)(g_U + ja * 256 + qtr * 64);
            #pragma unroll
            for (int kcL = 0; kcL < 4; kcL++) {
                float4 A0 = ui[kcL * 4],     A1 = ui[kcL * 4 + 1];
                float4 A2 = ui[kcL * 4 + 2], A3 = ui[kcL * 4 + 3];
                float4 B0 = uj[kcL * 4],     B1 = uj[kcL * 4 + 1];
                float4 B2 = uj[kcL * 4 + 2], B3 = uj[kcL * 4 + 3];
                unsigned w0 = h2pk(tanhf(A0.x + B0.x), tanhf(A0.y + B0.y));
                unsigned w1 = h2pk(tanhf(A0.z + B0.z), tanhf(A0.w + B0.w));
                unsigned w2 = h2pk(tanhf(A1.x + B1.x), tanhf(A1.y + B1.y));
                unsigned w3 = h2pk(tanhf(A1.z + B1.z), tanhf(A1.w + B1.w));
                unsigned w4 = h2pk(tanhf(A2.x + B2.x), tanhf(A2.y + B2.y));
                unsigned w5 = h2pk(tanhf(A2.z + B2.z), tanhf(A2.w + B2.w));
                unsigned w6 = h2pk(tanhf(A3.x + B3.x), tanhf(A3.y + B3.y));
                unsigned w7 = h2pk(tanhf(A3.z + B3.z), tanhf(A3.w + B3.w));
                const uint32_t tb = (uint32_t)((mt * 16 + qtr * 4 + kcL) * 512);
                st128s(su + OFF_H + tb + o0, w0, w1, w2, w3);
                st128s(su + OFF_H + tb + o1, w4, w5, w6, w7);
            }
        } else {
            #pragma unroll
            for (int kcL = 0; kcL < 4; kcL++) {
                const uint32_t tb = (uint32_t)((mt * 16 + qtr * 4 + kcL) * 512);
                st128s(su + OFF_H + tb + o0, 0, 0, 0, 0);
                st128s(su + OFF_H + tb + o1, 0, 0, 0, 0);
            }
        }
        // basis rows (zero-padded past mvalid): each thread one float4
        float4 b0;
        if (m < mvalid) b0 = ((const float4*)(basis + (size_t)(m0 + m) * 16))[qtr];
        else            b0 = make_float4(0.f, 0.f, 0.f, 0.f);
        float* bd = sBas + m * 17 + qtr * 4;
        bd[0] = b0.x; bd[1] = b0.y; bd[2] = b0.z; bd[3] = b0.w;
    }
    __syncthreads();

    const unsigned* pW2 = g_W2f + wn * 512 + lane * 4;   // per-t stride 2048

    float acc[2][8][4];
    #pragma unroll
    for (int mt = 0; mt < 2; mt++)
        #pragma unroll
        for (int nt = 0; nt < 8; nt++)
            #pragma unroll
            for (int e = 0; e < 4; e++) acc[mt][nt][e] = 0.f;

    // ====== GEMM2 fp16 (M=64 split 2x32, 8 passes x 16 ksteps, nt=8) ======
    const uint32_t aBase = aHB + (uint32_t)(wm * 2 * 16 * 512);
    uint4 D0 = *(const uint4*)(pW2),       D1 = *(const uint4*)(pW2 + 128);
    uint4 D2 = *(const uint4*)(pW2 + 256), D3 = *(const uint4*)(pW2 + 384);

    #pragma unroll 1
    for (int pass = 0; pass < 8; pass++) {
        #pragma unroll 2
        for (int kc = 0; kc < 16; kc++) {
            const int t = pass * 16 + kc;
            const unsigned* np = pW2 + (size_t)((t < 127) ? (t + 1) : 0) * 2048;
            uint4 N0 = *(const uint4*)(np),       N1 = *(const uint4*)(np + 128);
            uint4 N2 = *(const uint4*)(np + 256), N3 = *(const uint4*)(np + 384);
            const unsigned BH[8][2] = {{D0.x, D0.y}, {D0.z, D0.w}, {D1.x, D1.y}, {D1.z, D1.w},
                                       {D2.x, D2.y}, {D2.z, D2.w}, {D3.x, D3.y}, {D3.z, D3.w}};
            #pragma unroll
            for (int mt = 0; mt < 2; mt++) {
                unsigned a[4];
                ldm4(a, aBase + (uint32_t)((mt * 16 + kc) * 512));
                #pragma unroll
                for (int nt = 0; nt < 8; nt++)
                    mma4h(acc[mt][nt], a, BH[nt][0], BH[nt][1]);
            }
            D0 = N0; D1 = N1; D2 = N2; D3 = N3;
        }
        // epilogue: out[m][c] = sum_b H[m][16c+b]*basis[m][b]; warp owns 4 cols/pass
        #pragma unroll
        for (int mt = 0; mt < 2; mt++) {
            const int row0 = wm * 32 + mt * 16 + r, row1 = row0 + 8;
            float b00 = sBas[row0 * 17 + 2 * q],     b01 = sBas[row0 * 17 + 2 * q + 1];
            float b08 = sBas[row0 * 17 + 8 + 2 * q], b09 = sBas[row0 * 17 + 9 + 2 * q];
            float b10 = sBas[row1 * 17 + 2 * q],     b11 = sBas[row1 * 17 + 2 * q + 1];
            float b18 = sBas[row1 * 17 + 8 + 2 * q], b19 = sBas[row1 * 17 + 9 + 2 * q];
            #pragma unroll
            for (int tp = 0; tp < 4; tp++) {
                float s0 = acc[mt][2 * tp][0] * b00 + acc[mt][2 * tp][1] * b01
                         + acc[mt][2 * tp + 1][0] * b08 + acc[mt][2 * tp + 1][1] * b09;
                float s1 = acc[mt][2 * tp][2] * b10 + acc[mt][2 * tp][3] * b11
                         + acc[mt][2 * tp + 1][2] * b18 + acc[mt][2 * tp + 1][3] * b19;
                s0 += __shfl_xor_sync(0xffffffffu, s0, 1);
                s0 += __shfl_xor_sync(0xffffffffu, s0, 2);
                s1 += __shfl_xor_sync(0xffffffffu, s1, 1);
                s1 += __shfl_xor_sync(0xffffffffu, s1, 2);
                if (q == 0) {
                    const int c = pass * 16 + wn * 4 + tp;
                    sOut[row0 * 132 + c] = s0;
                    sOut[row1 * 132 + c] = s1;
                }
            }
            #pragma unroll
            for (int nt = 0; nt < 8; nt++)
                #pragma unroll
                for (int e = 0; e < 4; e++) acc[mt][nt][e] = 0.f;
        }
    }
    __syncthreads();

    // ---- coalesced output store ----
    #pragma unroll 1
    for (int i = tid; i < TM * 32; i += 256) {
        const int m = i >> 5, c4 = i & 31;
        if (m < mvalid) {
            const float4 v = *(const float4*)(sOut + m * 132 + c4 * 4);
            *(float4*)(out + ((size_t)(m0 + m)) * NIN + c4 * 4) = v;
        }
    }
}

extern "C" void kernel_launch(void* const* d_in, const int* in_sizes, int n_in,
                              void* d_out, int out_size) {
    const float* prop  = (const float*)d_in[0];
    const void*  idxi  = d_in[1];
    const void*  idxj  = d_in[2];
    const float* basis = (const float*)d_in[3];
    const float* W1    = (const float*)d_in[4];
    const float* W2    = (const float*)d_in[5];
    float* out = (float*)d_out;
    const int P = out_size / NIN;
    const int NN = in_sizes[0] / NIN;
    (void)n_in;

    cudaFuncSetAttribute(pilayer_kernel, cudaFuncAttributeMaxDynamicSharedMemorySize, SMEM_BYTES);
    cudaFuncSetAttribute(prep_u_kernel, cudaFuncAttributeMaxDynamicSharedMemorySize, SMEM_PREP);

    detect_idx_kernel<<<1, 32>>>((const unsigned*)idxi);
    prep_w1_kernel<<<64, 256>>>(W1);
    prep_w2_kernel<<<1024, 256>>>(W2);

    const int nblocks = (NN + TM - 1) / TM;
    prep_u_kernel<<<nblocks, 256, SMEM_PREP>>>(prop, NN);

    const int blocks = (P + TM - 1) / TM;
    pilayer_kernel<<<blocks, 256, SMEM_BYTES>>>(idxi, idxj, basis, out, P);
}